// round 9
// baseline (speedup 1.0000x reference)
#include <cuda_runtime.h>

#define DIMC 192
#define RJ   48          // DIM / RED
#define BB   4
#define HH   256
#define WW   256
#define HWSZ (HH * WW)   // 65536
#define EPSV 1e-5f
#define NPLANES (BB * DIMC)       // 768

// Scratch (no device allocation allowed).
__device__ float g_pooled[NPLANES];      // [b*DIM + c]
__device__ float g_wt[NPLANES * 4];      // 4 surviving masked taps per (b,c)

// ---------------------------------------------------------------------------
// Kernel 1: global average pool per (b,c). One block per channel plane.
// All 768 blocks co-resident (one wave), streaming planes in lockstep:
// at pool end L2 holds the tail rows of every plane. Default (evict-normal)
// loads on purpose — this residue is what conv will hit.
// ---------------------------------------------------------------------------
__global__ void pool_kernel(const float* __restrict__ x) {
    const int bc = blockIdx.x;                       // 0..767
    const float4* p = (const float4*)(x + (size_t)bc * HWSZ);
    const int n4 = HWSZ / 4;                         // 16384
    float s = 0.f;
    for (int i = threadIdx.x; i < n4; i += blockDim.x) {
        float4 v = p[i];
        s += (v.x + v.y) + (v.z + v.w);
    }
    #pragma unroll
    for (int o = 16; o > 0; o >>= 1) s += __shfl_down_sync(0xffffffffu, s, o);
    __shared__ float sm[32];
    const int lane = threadIdx.x & 31;
    const int wrp  = threadIdx.x >> 5;
    if (lane == 0) sm[wrp] = s;
    __syncthreads();
    if (wrp == 0) {
        s = (lane < (int)(blockDim.x >> 5)) ? sm[lane] : 0.f;
        #pragma unroll
        for (int o = 16; o > 0; o >>= 1) s += __shfl_down_sync(0xffffffffu, s, o);
        if (lane == 0) g_pooled[bc] = s * (1.0f / (float)HWSZ);
    }
}

// ---------------------------------------------------------------------------
// Kernel 2: dynamic weight generation (tiny, unchanged).
// ---------------------------------------------------------------------------
__global__ void wgen_kernel(const float* __restrict__ w1,
                            const float* __restrict__ gamma,
                            const float* __restrict__ beta,
                            const float* __restrict__ rmean,
                            const float* __restrict__ rvar,
                            const float* __restrict__ w2,
                            const float* __restrict__ b2) {
    const int b   = blockIdx.x;
    const int tid = threadIdx.x;
    __shared__ float t[RJ];

    if (tid < RJ) {
        const float* pw = w1 + tid * DIMC;
        const float* pp = g_pooled + b * DIMC;
        float acc = 0.f;
        #pragma unroll 8
        for (int c = 0; c < DIMC; c++) acc = fmaf(pp[c], pw[c], acc);
        acc = gamma[tid] * (acc - rmean[tid]) * rsqrtf(rvar[tid] + EPSV) + beta[tid];
        t[tid] = fmaxf(acc, 0.f);
    }
    __syncthreads();

    // tid -> (channel c, tap k). Mask 'A' keeps 3x3 positions 0..3.
    const int c = tid >> 2;
    const int k = tid & 3;
    const int o = c * 9 + k;
    const float* pw2 = w2 + (size_t)o * RJ;
    float acc = b2[o];
    #pragma unroll
    for (int j = 0; j < RJ; j++) acc = fmaf(t[j], pw2[j], acc);
    g_wt[(b * DIMC + c) * 4 + k] = acc;
}

// ---------------------------------------------------------------------------
// Kernel 3: masked depthwise conv. Active taps:
//   out(y,x) = w0*in(y-1,x-1)+w1*in(y-1,x)+w2*in(y-1,x+1)+w3*in(y,x-1)+bias
// One warp = one full image row. 4 LDG + 2 STG per thread, shuffle halos.
// R7-proven ordering: grid (32, 768), planes reversed via blockIdx.y.
// NEW: __ldlu reads (last-use: invalidate after hit, frees L2 for untouched
// pool residue) and __stwt writes (write-through: no L2 write-allocate churn).
// ---------------------------------------------------------------------------
__global__ __launch_bounds__(256) void conv_kernel(const float* __restrict__ x,
                                                   const float* __restrict__ bias,
                                                   float* __restrict__ out) {
    const int bc = (NPLANES - 1) - blockIdx.y;      // reversed: 767..0
    const int c  = bc % DIMC;
    const float4 wv = *(const float4*)(g_wt + bc * 4);
    const float w0 = wv.x, w1 = wv.y, w2 = wv.z, w3 = wv.w;
    const float bs = bias[c];

    const int lane = threadIdx.x & 31;
    const int y    = blockIdx.x * 8 + (threadIdx.x >> 5);
    const int x0   = lane << 3;                     // 8 floats per thread

    const float* base = x + (size_t)bc * HWSZ;
    const float* rowc = base + y * WW;
    const float* rowm = rowc - WW;                  // deref'd only when y>0 (warp-uniform)

    const float4 b0 = __ldlu((const float4*)(rowc + x0));
    const float4 b1 = __ldlu((const float4*)(rowc + x0 + 4));

    float4 a0, a1;
    if (y > 0) {                                     // warp-uniform
        a0 = __ldlu((const float4*)(rowm + x0));
        a1 = __ldlu((const float4*)(rowm + x0 + 4));
    } else {
        a0 = make_float4(0.f, 0.f, 0.f, 0.f); a1 = a0;
    }

    float am1 = __shfl_up_sync(0xffffffffu, a1.w, 1);
    float bm1 = __shfl_up_sync(0xffffffffu, b1.w, 1);
    float ap8 = __shfl_down_sync(0xffffffffu, a0.x, 1);
    if (lane == 0)  { am1 = 0.f; bm1 = 0.f; }
    if (lane == 31) { ap8 = 0.f; }

    const float A[10] = {am1, a0.x, a0.y, a0.z, a0.w, a1.x, a1.y, a1.z, a1.w, ap8};
    const float Bv[8] = {bm1, b0.x, b0.y, b0.z, b0.w, b1.x, b1.y, b1.z};

    float o[8];
    #pragma unroll
    for (int i = 0; i < 8; i++)
        o[i] = fmaf(w0, A[i], fmaf(w1, A[i+1], fmaf(w2, A[i+2], fmaf(w3, Bv[i], bs))));

    float* po = out + (size_t)bc * HWSZ + y * WW + x0;
    __stwt((float4*)po,     make_float4(o[0], o[1], o[2], o[3]));
    __stwt((float4*)po + 1, make_float4(o[4], o[5], o[6], o[7]));
}

// ---------------------------------------------------------------------------
extern "C" void kernel_launch(void* const* d_in, const int* in_sizes, int n_in,
                              void* d_out, int out_size) {
    const float* x     = (const float*)d_in[0];
    const float* w1    = (const float*)d_in[1];
    const float* gamma = (const float*)d_in[2];
    const float* beta  = (const float*)d_in[3];
    const float* rmean = (const float*)d_in[4];
    const float* rvar  = (const float*)d_in[5];
    const float* w2    = (const float*)d_in[6];
    const float* b2    = (const float*)d_in[7];
    const float* bias  = (const float*)d_in[8];
    float* out = (float*)d_out;

    pool_kernel<<<NPLANES, 256>>>(x);
    wgen_kernel<<<BB, DIMC * 4>>>(w1, gamma, beta, rmean, rvar, w2, b2);

    dim3 grid(HH / 8, NPLANES);                     // (32, 768), y = reversed plane
    conv_kernel<<<grid, 256>>>(x, bias, out);
}

// round 10
// speedup vs baseline: 1.0859x; 1.0859x over previous
#include <cuda_runtime.h>

#define DIMC 192
#define RJ   48          // DIM / RED
#define BB   4
#define HH   256
#define WW   256
#define HWSZ (HH * WW)   // 65536
#define EPSV 1e-5f
#define NPLANES (BB * DIMC)       // 768

// Scratch (no device allocation allowed).
__device__ float g_pooled[NPLANES];      // [b*DIM + c]
__device__ float g_wt[NPLANES * 4];      // 4 surviving masked taps per (b,c)

// ---------------------------------------------------------------------------
// Kernel 1: global average pool per (b,c). One block per channel plane.
// At the LTS/HBM ceiling (6.25 TB/s) — frozen.
// ---------------------------------------------------------------------------
__global__ void pool_kernel(const float* __restrict__ x) {
    const int bc = blockIdx.x;                       // 0..767
    const float4* p = (const float4*)(x + (size_t)bc * HWSZ);
    const int n4 = HWSZ / 4;                         // 16384
    float s = 0.f;
    for (int i = threadIdx.x; i < n4; i += blockDim.x) {
        float4 v = p[i];
        s += (v.x + v.y) + (v.z + v.w);
    }
    #pragma unroll
    for (int o = 16; o > 0; o >>= 1) s += __shfl_down_sync(0xffffffffu, s, o);
    __shared__ float sm[32];
    const int lane = threadIdx.x & 31;
    const int wrp  = threadIdx.x >> 5;
    if (lane == 0) sm[wrp] = s;
    __syncthreads();
    if (wrp == 0) {
        s = (lane < (int)(blockDim.x >> 5)) ? sm[lane] : 0.f;
        #pragma unroll
        for (int o = 16; o > 0; o >>= 1) s += __shfl_down_sync(0xffffffffu, s, o);
        if (lane == 0) g_pooled[bc] = s * (1.0f / (float)HWSZ);
    }
}

// ---------------------------------------------------------------------------
// Kernel 2: dynamic weight generation (tiny, unchanged).
// ---------------------------------------------------------------------------
__global__ void wgen_kernel(const float* __restrict__ w1,
                            const float* __restrict__ gamma,
                            const float* __restrict__ beta,
                            const float* __restrict__ rmean,
                            const float* __restrict__ rvar,
                            const float* __restrict__ w2,
                            const float* __restrict__ b2) {
    const int b   = blockIdx.x;
    const int tid = threadIdx.x;
    __shared__ float t[RJ];

    if (tid < RJ) {
        const float* pw = w1 + tid * DIMC;
        const float* pp = g_pooled + b * DIMC;
        float acc = 0.f;
        #pragma unroll 8
        for (int c = 0; c < DIMC; c++) acc = fmaf(pp[c], pw[c], acc);
        acc = gamma[tid] * (acc - rmean[tid]) * rsqrtf(rvar[tid] + EPSV) + beta[tid];
        t[tid] = fmaxf(acc, 0.f);
    }
    __syncthreads();

    // tid -> (channel c, tap k). Mask 'A' keeps 3x3 positions 0..3.
    const int c = tid >> 2;
    const int k = tid & 3;
    const int o = c * 9 + k;
    const float* pw2 = w2 + (size_t)o * RJ;
    float acc = b2[o];
    #pragma unroll
    for (int j = 0; j < RJ; j++) acc = fmaf(t[j], pw2[j], acc);
    g_wt[(b * DIMC + c) * 4 + k] = acc;
}

// ---------------------------------------------------------------------------
// Kernel 3: masked depthwise conv. Active taps:
//   out(y,x) = w0*in(y-1,x-1)+w1*in(y-1,x)+w2*in(y-1,x+1)+w3*in(y,x-1)+bias
// One warp = one full image row. 4 LDG.128 + 2 STG.128 per thread, halos via
// warp shuffles (lane 0/31 = true edge zeros). Reversed-plane order (R7 win).
// DEFAULT cached loads: warp w+1's row-above load L1-hits the line warp w
// just loaded as its current row -> halves LTS read traffic vs __ldcs.
// ---------------------------------------------------------------------------
__global__ __launch_bounds__(256) void conv_kernel(const float* __restrict__ x,
                                                   const float* __restrict__ bias,
                                                   float* __restrict__ out) {
    const int bc = (NPLANES - 1) - blockIdx.y;      // reversed: 767..0
    const int c  = bc % DIMC;
    const float4 wv = *(const float4*)(g_wt + bc * 4);
    const float w0 = wv.x, w1 = wv.y, w2 = wv.z, w3 = wv.w;
    const float bs = bias[c];

    const int lane = threadIdx.x & 31;
    const int y    = blockIdx.x * 8 + (threadIdx.x >> 5);
    const int x0   = lane << 3;                     // 8 floats per thread

    const float* base = x + (size_t)bc * HWSZ;
    const float* rowc = base + y * WW;
    const float* rowm = rowc - WW;                  // deref'd only when y>0 (warp-uniform)

    const float4 b0 = *(const float4*)(rowc + x0);
    const float4 b1 = *(const float4*)(rowc + x0 + 4);

    float4 a0, a1;
    if (y > 0) {                                     // warp-uniform
        a0 = *(const float4*)(rowm + x0);
        a1 = *(const float4*)(rowm + x0 + 4);
    } else {
        a0 = make_float4(0.f, 0.f, 0.f, 0.f); a1 = a0;
    }

    float am1 = __shfl_up_sync(0xffffffffu, a1.w, 1);
    float bm1 = __shfl_up_sync(0xffffffffu, b1.w, 1);
    float ap8 = __shfl_down_sync(0xffffffffu, a0.x, 1);
    if (lane == 0)  { am1 = 0.f; bm1 = 0.f; }
    if (lane == 31) { ap8 = 0.f; }

    const float A[10] = {am1, a0.x, a0.y, a0.z, a0.w, a1.x, a1.y, a1.z, a1.w, ap8};
    const float Bv[8] = {bm1, b0.x, b0.y, b0.z, b0.w, b1.x, b1.y, b1.z};

    float o[8];
    #pragma unroll
    for (int i = 0; i < 8; i++)
        o[i] = fmaf(w0, A[i], fmaf(w1, A[i+1], fmaf(w2, A[i+2], fmaf(w3, Bv[i], bs))));

    float* po = out + (size_t)bc * HWSZ + y * WW + x0;
    __stcs((float4*)po,     make_float4(o[0], o[1], o[2], o[3]));
    __stcs((float4*)po + 1, make_float4(o[4], o[5], o[6], o[7]));
}

// ---------------------------------------------------------------------------
extern "C" void kernel_launch(void* const* d_in, const int* in_sizes, int n_in,
                              void* d_out, int out_size) {
    const float* x     = (const float*)d_in[0];
    const float* w1    = (const float*)d_in[1];
    const float* gamma = (const float*)d_in[2];
    const float* beta  = (const float*)d_in[3];
    const float* rmean = (const float*)d_in[4];
    const float* rvar  = (const float*)d_in[5];
    const float* w2    = (const float*)d_in[6];
    const float* b2    = (const float*)d_in[7];
    const float* bias  = (const float*)d_in[8];
    float* out = (float*)d_out;

    pool_kernel<<<NPLANES, 256>>>(x);
    wgen_kernel<<<BB, DIMC * 4>>>(w1, gamma, beta, rmean, rvar, w2, b2);

    dim3 grid(HH / 8, NPLANES);                     // (32, 768), y = reversed plane
    conv_kernel<<<grid, 256>>>(x, bias, out);
}